// round 12
// baseline (speedup 1.0000x reference)
#include <cuda_runtime.h>
#include <cuda_fp16.h>
#include <cstdint>

#define VOCAB 30000
#define EMB 128
#define ENC 128
#define BS 256
#define NNODES 1023

// Precomputed P[t][o] = dot(emb[t,:], W_c[o,:]) + b_c[o], stored fp16 (7.7 MB).
__device__ __half g_Ph[VOCAB * ENC];

// ---------------------------------------------------------------------------
// Kernel A: P = emb @ W_c^T + b_c via mma.sync m16n8k16 fp16 (HMMA, fp32 acc).
//   469 CTAs x 256 thr, 52 KB smem, 4 CTA/SM, one wave. Triggers PDL
//   completion after its P stores.
// ---------------------------------------------------------------------------
#define MT 64
#define SAS 136   // smem row stride in fp16 elements (272 B: ldmatrix conflict-free)

#define MMA16816(c, a, b)                                                   \
    asm("mma.sync.aligned.m16n8k16.row.col.f32.f16.f16.f32 "                \
        "{%0,%1,%2,%3}, {%4,%5,%6,%7}, {%8,%9}, {%0,%1,%2,%3};"             \
        : "+f"((c)[0]), "+f"((c)[1]), "+f"((c)[2]), "+f"((c)[3])            \
        : "r"((a)[0]), "r"((a)[1]), "r"((a)[2]), "r"((a)[3]),               \
          "r"((b)[0]), "r"((b)[1]))

#define LDMX4(r, addr)                                                      \
    asm volatile("ldmatrix.sync.aligned.m8n8.x4.shared.b16 "                \
                 "{%0,%1,%2,%3}, [%4];"                                     \
                 : "=r"((r)[0]), "=r"((r)[1]), "=r"((r)[2]), "=r"((r)[3])   \
                 : "r"(addr))

__device__ __forceinline__ uint32_t su32(const void* p) {
    return (uint32_t)__cvta_generic_to_shared(p);
}

__device__ __forceinline__ void cvt_store(uint16_t* __restrict__ dst, int off, float4 x) {
    __half2 p01 = __floats2half2_rn(x.x, x.y);
    __half2 p23 = __floats2half2_rn(x.z, x.w);
    *(uint2*)(dst + off) = make_uint2(*(uint32_t*)&p01, *(uint32_t*)&p23);
}

__global__ void __launch_bounds__(256) pmat_kernel(const float* __restrict__ emb,
                                                   const float* __restrict__ Wc,
                                                   const float* __restrict__ bc) {
    extern __shared__ __align__(16) char dsm[];
    uint16_t* sA = (uint16_t*)dsm;                     // 64*136*2  = 17408 B
    uint16_t* sB = (uint16_t*)(dsm + 17408);           // 128*136*2 = 34816 B
    __shared__ float s_bias[128];

    const int tid = threadIdx.x;
    const int row0 = blockIdx.x * MT;

    if (tid < 128) s_bias[tid] = bc[tid];

    #pragma unroll 2
    for (int i = tid; i < MT * 32; i += 256) {
        int r = i >> 5, q = (i & 31) * 4;
        float4 x = make_float4(0.f, 0.f, 0.f, 0.f);
        if (row0 + r < VOCAB) x = *(const float4*)(emb + (size_t)(row0 + r) * 128 + q);
        cvt_store(sA, r * SAS + q, x);
    }
    #pragma unroll 4
    for (int i = tid; i < 128 * 32; i += 256) {
        int r = i >> 5, q = (i & 31) * 4;
        float4 w = *(const float4*)(Wc + (size_t)r * 128 + q);
        cvt_store(sB, r * SAS + q, w);
    }
    __syncthreads();

    const int warp = tid >> 5, lane = tid & 31;
    const int grp = lane >> 2, t4 = lane & 3;
    const int quad = lane >> 3, r8 = lane & 7;
    const int m0 = (warp & 1) * 32;
    const int n0 = (warp >> 1) * 32;

    uint32_t aA[2];
    #pragma unroll
    for (int mt = 0; mt < 2; mt++) {
        int rowA = m0 + mt * 16 + (quad & 1) * 8 + r8;
        int kA = (quad >> 1) * 8;
        aA[mt] = su32(sA) + (rowA * SAS + kA) * 2;
    }
    uint32_t aB[2];
    #pragma unroll
    for (int i = 0; i < 2; i++) {
        int rowB = n0 + i * 16 + (quad >> 1) * 8 + r8;
        int kB = (quad & 1) * 8;
        aB[i] = su32(sB) + (rowB * SAS + kB) * 2;
    }

    float acc[2][4][4];
    #pragma unroll
    for (int mt = 0; mt < 2; mt++)
        #pragma unroll
        for (int nt = 0; nt < 4; nt++)
            #pragma unroll
            for (int j = 0; j < 4; j++) acc[mt][nt][j] = 0.f;

    #pragma unroll
    for (int ks = 0; ks < 8; ks++) {
        const uint32_t off = ks * 32;
        uint32_t a[2][4];
        LDMX4(a[0], aA[0] + off);
        LDMX4(a[1], aA[1] + off);
        uint32_t bp[2][4];
        LDMX4(bp[0], aB[0] + off);
        LDMX4(bp[1], aB[1] + off);
        #pragma unroll
        for (int mt = 0; mt < 2; mt++)
            #pragma unroll
            for (int nt = 0; nt < 4; nt++) {
                uint32_t* bb = &bp[nt >> 1][(nt & 1) * 2];
                MMA16816(acc[mt][nt], a[mt], bb);
            }
    }

    #pragma unroll
    for (int mt = 0; mt < 2; mt++) {
        #pragma unroll
        for (int nt = 0; nt < 4; nt++) {
            int col = n0 + nt * 8 + t4 * 2;
            float b0 = s_bias[col], b1 = s_bias[col + 1];
            int r_lo = row0 + m0 + mt * 16 + grp;
            if (r_lo < VOCAB) {
                __half2 v = __floats2half2_rn(acc[mt][nt][0] + b0, acc[mt][nt][1] + b1);
                *(__half2*)(g_Ph + (size_t)r_lo * 128 + col) = v;
            }
            int r_hi = r_lo + 8;
            if (r_hi < VOCAB) {
                __half2 v = __floats2half2_rn(acc[mt][nt][2] + b0, acc[mt][nt][3] + b1);
                *(__half2*)(g_Ph + (size_t)r_hi * 128 + col) = v;
            }
        }
    }

    // PDL: P writes above are flushed-visible to the dependent grid.
    cudaTriggerProgrammaticLaunchCompletion();
}

// ---------------------------------------------------------------------------
// Kernel B: per (batch, channel-half) CTA: bottom-up subtree sums + max.
//   R10 body (32 regs, occ ~78%) + PDL: stages tokens (independent of P),
//   then cudaGridDependencySynchronize() before gathering from g_Ph.
// ---------------------------------------------------------------------------
__device__ __forceinline__ float2 f2add(float2 a, float2 b) {
    return make_float2(a.x + b.x, a.y + b.y);
}
__device__ __forceinline__ float2 f2max(float2 a, float2 b) {
    return make_float2(fmaxf(a.x, b.x), fmaxf(a.y, b.y));
}
__device__ __forceinline__ __half2 asH2(uint32_t u) { return *(__half2*)&u; }
__device__ __forceinline__ float2 ldPf(const uint32_t* p) {
    uint32_t u = __ldg(p);
    return __half22float2(asH2(u));
}

__global__ void __launch_bounds__(512) tree_kernel(const int* __restrict__ tokens,
                                                   float* __restrict__ out) {
    __shared__ __align__(16) int stok[1024];   // token i at stok[i+1] (alignment shift)
    __shared__ float2 bufA[64 * 32];           // 16 KB
    __shared__ float2 bufB[32 * 32];           //  8 KB

    const int bh   = blockIdx.x;
    const int b    = bh >> 1;
    const int chb  = (bh & 1) << 6;
    const int tid  = threadIdx.x;
    const int lane = tid & 31;
    const int grp  = tid >> 5;           // 0..15
    const int* tokrow = tokens + (size_t)b * NNODES;

    // Stage tokens — independent of pmat's output, overlaps pmat tail via PDL.
    for (int i = tid; i < NNODES; i += 512) stok[i + 1] = tokrow[i];

    // Wait for pmat's P stores to be visible before any g_Ph gather.
    cudaGridDependencySynchronize();
    __syncthreads();

    // node t -> Pc[t*64]; each uint32 = half2 = 2 channels
    const uint32_t* Pc = (const uint32_t*)g_Ph + (chb >> 1) + lane;
    float2 maxv = make_float2(-3.4e38f, -3.4e38f);
    __half2 hmax = __float2half2_rn(-65504.f);

    // fused levels 9..6: 64 subtrees rooted at level-6 nodes q = 63+m
    #pragma unroll
    for (int mi = 0; mi < 4; mi++) {
        int m = grp + mi * 16;
        int q = 63 + m;
        int  tq  = stok[q + 1];
        int2 t2  = *(const int2*)&stok[2 * q + 2];
        int4 t4v = *(const int4*)&stok[4 * q + 4];
        int4 t8a = *(const int4*)&stok[8 * q + 8];
        int4 t8b = *(const int4*)&stok[8 * q + 12];

        uint32_t uq, u2[2], u4[4], u8[8];
        uq    = __ldg(Pc + (size_t)tq * 64);
        u2[0] = __ldg(Pc + (size_t)t2.x * 64);
        u2[1] = __ldg(Pc + (size_t)t2.y * 64);
        u4[0] = __ldg(Pc + (size_t)t4v.x * 64);
        u4[1] = __ldg(Pc + (size_t)t4v.y * 64);
        u4[2] = __ldg(Pc + (size_t)t4v.z * 64);
        u4[3] = __ldg(Pc + (size_t)t4v.w * 64);
        u8[0] = __ldg(Pc + (size_t)t8a.x * 64);
        u8[1] = __ldg(Pc + (size_t)t8a.y * 64);
        u8[2] = __ldg(Pc + (size_t)t8a.z * 64);
        u8[3] = __ldg(Pc + (size_t)t8a.w * 64);
        u8[4] = __ldg(Pc + (size_t)t8b.x * 64);
        u8[5] = __ldg(Pc + (size_t)t8b.y * 64);
        u8[6] = __ldg(Pc + (size_t)t8b.z * 64);
        u8[7] = __ldg(Pc + (size_t)t8b.w * 64);

        // leaf max (exact fp16 compares)
        __half2 lm01 = __hmax2(asH2(u8[0]), asH2(u8[1]));
        __half2 lm23 = __hmax2(asH2(u8[2]), asH2(u8[3]));
        __half2 lm45 = __hmax2(asH2(u8[4]), asH2(u8[5]));
        __half2 lm67 = __hmax2(asH2(u8[6]), asH2(u8[7]));
        hmax = __hmax2(hmax, __hmax2(__hmax2(lm01, lm23), __hmax2(lm45, lm67)));

        // level-8 sums in fp16
        __half2 s8h[4];
        #pragma unroll
        for (int j = 0; j < 4; j++) {
            s8h[j] = __hadd2(asH2(u4[j]), __hadd2(asH2(u8[2 * j]), asH2(u8[2 * j + 1])));
            hmax = __hmax2(hmax, s8h[j]);
        }

        // upper part of subtree in fp32
        float2 f80 = __half22float2(s8h[0]);
        float2 f81 = __half22float2(s8h[1]);
        float2 f82 = __half22float2(s8h[2]);
        float2 f83 = __half22float2(s8h[3]);
        float2 s70 = f2add(__half22float2(asH2(u2[0])), f2add(f80, f81));
        float2 s71 = f2add(__half22float2(asH2(u2[1])), f2add(f82, f83));
        maxv = f2max(maxv, f2max(s70, s71));
        float2 s6 = f2add(__half22float2(asH2(uq)), f2add(s70, s71));
        maxv = f2max(maxv, s6);
        bufA[m * 32 + lane] = s6;
    }
    maxv = f2max(maxv, __half22float2(hmax));
    __syncthreads();

    #pragma unroll
    for (int ii = 0; ii < 2; ii++) {             // l5: A(64)->B(32)
        int i = grp + ii * 16;
        float2 v = f2add(f2add(bufA[(2 * i) * 32 + lane], bufA[(2 * i + 1) * 32 + lane]),
                         ldPf(Pc + (size_t)stok[32 + i] * 64));
        maxv = f2max(maxv, v);
        bufB[i * 32 + lane] = v;
    }
    __syncthreads();
    {                                            // l4: B(32)->A(16)
        int i = grp;
        float2 v = f2add(f2add(bufB[(2 * i) * 32 + lane], bufB[(2 * i + 1) * 32 + lane]),
                         ldPf(Pc + (size_t)stok[16 + i] * 64));
        maxv = f2max(maxv, v);
        bufA[i * 32 + lane] = v;
    }
    __syncthreads();
    if (grp < 8) {                               // l3: A(16)->B(8)
        int i = grp;
        float2 v = f2add(f2add(bufA[(2 * i) * 32 + lane], bufA[(2 * i + 1) * 32 + lane]),
                         ldPf(Pc + (size_t)stok[8 + i] * 64));
        maxv = f2max(maxv, v);
        bufB[i * 32 + lane] = v;
    }
    __syncthreads();
    if (grp < 4) {                               // l2: B(8)->A(4)
        int i = grp;
        float2 v = f2add(f2add(bufB[(2 * i) * 32 + lane], bufB[(2 * i + 1) * 32 + lane]),
                         ldPf(Pc + (size_t)stok[4 + i] * 64));
        maxv = f2max(maxv, v);
        bufA[i * 32 + lane] = v;
    }
    __syncthreads();
    if (grp < 2) {                               // l1: A(4)->B(2)
        int i = grp;
        float2 v = f2add(f2add(bufA[(2 * i) * 32 + lane], bufA[(2 * i + 1) * 32 + lane]),
                         ldPf(Pc + (size_t)stok[2 + i] * 64));
        maxv = f2max(maxv, v);
        bufB[i * 32 + lane] = v;
    }
    __syncthreads();
    if (grp == 0) {                              // l0: root
        float2 v = f2add(f2add(bufB[lane], bufB[32 + lane]),
                         ldPf(Pc + (size_t)stok[1] * 64));
        maxv = f2max(maxv, v);
    }

    // cross-group max (reuse bufA: [grp][lane])
    bufA[grp * 32 + lane] = maxv;
    __syncthreads();
    if (grp == 0) {
        float2 m = bufA[lane];
        #pragma unroll
        for (int g = 1; g < 16; g++) m = f2max(m, bufA[g * 32 + lane]);
        *(float2*)(out + (size_t)b * 128 + chb + 2 * lane) = m;
    }
}

// ---------------------------------------------------------------------------
// kernel_launch: pmat, then tree launched with PDL so its token staging
// overlaps pmat's tail.
// ---------------------------------------------------------------------------
extern "C" void kernel_launch(void* const* d_in, const int* in_sizes, int n_in,
                              void* d_out, int out_size) {
    const int*   tokens = (const int*)d_in[0];
    const float* emb    = (const float*)d_in[1];
    const float* Wc     = (const float*)d_in[2];
    const float* bc     = (const float*)d_in[3];
    float*       out    = (float*)d_out;

    const int smemA = 17408 + 34816;   // 52224 B -> 4 CTAs/SM
    cudaFuncSetAttribute(pmat_kernel, cudaFuncAttributeMaxDynamicSharedMemorySize, smemA);

    const int gridA = (VOCAB + MT - 1) / MT;   // 469
    pmat_kernel<<<gridA, 256, smemA>>>(emb, Wc, bc);

    cudaLaunchConfig_t cfg = {};
    cfg.gridDim  = dim3(BS * 2, 1, 1);
    cfg.blockDim = dim3(512, 1, 1);
    cfg.dynamicSmemBytes = 0;
    cudaLaunchAttribute attrs[1];
    attrs[0].id = cudaLaunchAttributeProgrammaticStreamSerialization;
    attrs[0].val.programmaticStreamSerializationAllowed = 1;
    cfg.attrs = attrs;
    cfg.numAttrs = 1;
    cudaLaunchKernelEx(&cfg, tree_kernel, tokens, out);
}

// round 13
// speedup vs baseline: 1.1081x; 1.1081x over previous
#include <cuda_runtime.h>
#include <cuda_fp16.h>
#include <cstdint>

#define VOCAB 30000
#define EMB 128
#define ENC 128
#define BS 256
#define NNODES 1023

// Precomputed P[t][o] = dot(emb[t,:], W_c[o,:]) + b_c[o], stored fp16 (7.7 MB).
__device__ __half g_Ph[VOCAB * ENC];

// ---------------------------------------------------------------------------
// Kernel A: P = emb @ W_c^T + b_c via mma.sync m16n8k16 fp16 (HMMA, fp32 acc).
//   M-tile 128 (235 CTAs): W convert amortized 2x vs MT=64; warp = 32x64 tile,
//   16 HMMA per 6 ldmatrix. ~100 regs, 70 KB smem -> 2 CTA/SM, one wave.
// ---------------------------------------------------------------------------
#define MT 128
#define SAS 136   // smem row stride in fp16 elements (272 B: ldmatrix conflict-free)

#define MMA16816(c, a, b)                                                   \
    asm("mma.sync.aligned.m16n8k16.row.col.f32.f16.f16.f32 "                \
        "{%0,%1,%2,%3}, {%4,%5,%6,%7}, {%8,%9}, {%0,%1,%2,%3};"             \
        : "+f"((c)[0]), "+f"((c)[1]), "+f"((c)[2]), "+f"((c)[3])            \
        : "r"((a)[0]), "r"((a)[1]), "r"((a)[2]), "r"((a)[3]),               \
          "r"((b)[0]), "r"((b)[1]))

#define LDMX4(r, addr)                                                      \
    asm volatile("ldmatrix.sync.aligned.m8n8.x4.shared.b16 "                \
                 "{%0,%1,%2,%3}, [%4];"                                     \
                 : "=r"((r)[0]), "=r"((r)[1]), "=r"((r)[2]), "=r"((r)[3])   \
                 : "r"(addr))

__device__ __forceinline__ uint32_t su32(const void* p) {
    return (uint32_t)__cvta_generic_to_shared(p);
}

__device__ __forceinline__ void cvt_store(uint16_t* __restrict__ dst, int off, float4 x) {
    __half2 p01 = __floats2half2_rn(x.x, x.y);
    __half2 p23 = __floats2half2_rn(x.z, x.w);
    *(uint2*)(dst + off) = make_uint2(*(uint32_t*)&p01, *(uint32_t*)&p23);
}

__global__ void __launch_bounds__(256) pmat_kernel(const float* __restrict__ emb,
                                                   const float* __restrict__ Wc,
                                                   const float* __restrict__ bc) {
    extern __shared__ __align__(16) char dsm[];
    uint16_t* sA = (uint16_t*)dsm;                     // 128*136*2 = 34816 B
    uint16_t* sB = (uint16_t*)(dsm + 34816);           // 34816 B
    __shared__ float s_bias[128];

    const int tid = threadIdx.x;
    const int row0 = blockIdx.x * MT;

    if (tid < 128) s_bias[tid] = bc[tid];

    // ---- A tile: 128 rows, load fp32 -> fp16 ----
    #pragma unroll 4
    for (int i = tid; i < MT * 32; i += 256) {
        int r = i >> 5, q = (i & 31) * 4;
        float4 x = make_float4(0.f, 0.f, 0.f, 0.f);
        if (row0 + r < VOCAB) x = *(const float4*)(emb + (size_t)(row0 + r) * 128 + q);
        cvt_store(sA, r * SAS + q, x);
    }
    // ---- B = W_c: load fp32 -> fp16 (once per 128 output rows now) ----
    #pragma unroll 4
    for (int i = tid; i < 128 * 32; i += 256) {
        int r = i >> 5, q = (i & 31) * 4;
        float4 w = *(const float4*)(Wc + (size_t)r * 128 + q);
        cvt_store(sB, r * SAS + q, w);
    }
    __syncthreads();

    const int warp = tid >> 5, lane = tid & 31;
    const int grp = lane >> 2, t4 = lane & 3;
    const int quad = lane >> 3, r8 = lane & 7;
    const int m0 = (warp & 3) * 32;        // 4 m-groups
    const int n0 = (warp >> 2) * 64;       // 2 n-halves

    // ldmatrix lane base addresses (bytes).
    uint32_t aA[2];
    #pragma unroll
    for (int mt = 0; mt < 2; mt++) {
        int rowA = m0 + mt * 16 + (quad & 1) * 8 + r8;
        int kA = (quad >> 1) * 8;
        aA[mt] = su32(sA) + (rowA * SAS + kA) * 2;
    }
    uint32_t aB[4];
    #pragma unroll
    for (int i = 0; i < 4; i++) {
        int rowB = n0 + i * 16 + (quad >> 1) * 8 + r8;
        int kB = (quad & 1) * 8;
        aB[i] = su32(sB) + (rowB * SAS + kB) * 2;
    }

    float acc[2][8][4];
    #pragma unroll
    for (int mt = 0; mt < 2; mt++)
        #pragma unroll
        for (int nt = 0; nt < 8; nt++)
            #pragma unroll
            for (int j = 0; j < 4; j++) acc[mt][nt][j] = 0.f;

    #pragma unroll
    for (int ks = 0; ks < 8; ks++) {
        const uint32_t off = ks * 32;                  // 16 fp16 = 32 B per k-step
        uint32_t a[2][4];
        LDMX4(a[0], aA[0] + off);
        LDMX4(a[1], aA[1] + off);
        uint32_t bp[4][4];   // bp[i] = {b[2i][0], b[2i][1], b[2i+1][0], b[2i+1][1]}
        LDMX4(bp[0], aB[0] + off);
        LDMX4(bp[1], aB[1] + off);
        LDMX4(bp[2], aB[2] + off);
        LDMX4(bp[3], aB[3] + off);
        #pragma unroll
        for (int mt = 0; mt < 2; mt++)
            #pragma unroll
            for (int nt = 0; nt < 8; nt++) {
                uint32_t* bb = &bp[nt >> 1][(nt & 1) * 2];
                MMA16816(acc[mt][nt], a[mt], bb);
            }
    }

    // ---- epilogue: (D + bias) -> fp16 -> g_Ph ----
    #pragma unroll
    for (int mt = 0; mt < 2; mt++) {
        #pragma unroll
        for (int nt = 0; nt < 8; nt++) {
            int col = n0 + nt * 8 + t4 * 2;
            float b0 = s_bias[col], b1 = s_bias[col + 1];
            int r_lo = row0 + m0 + mt * 16 + grp;
            if (r_lo < VOCAB) {
                __half2 v = __floats2half2_rn(acc[mt][nt][0] + b0, acc[mt][nt][1] + b1);
                *(__half2*)(g_Ph + (size_t)r_lo * 128 + col) = v;
            }
            int r_hi = r_lo + 8;
            if (r_hi < VOCAB) {
                __half2 v = __floats2half2_rn(acc[mt][nt][2] + b0, acc[mt][nt][3] + b1);
                *(__half2*)(g_Ph + (size_t)r_hi * 128 + col) = v;
            }
        }
    }

    // PDL: P writes above are flushed-visible to the dependent grid.
    cudaTriggerProgrammaticLaunchCompletion();
}

// ---------------------------------------------------------------------------
// Kernel B: per (batch, channel-half) CTA: bottom-up subtree sums + max.
//   (R10/R12 body, 32 regs, occ ~78%.) PDL-gated gathers.
// ---------------------------------------------------------------------------
__device__ __forceinline__ float2 f2add(float2 a, float2 b) {
    return make_float2(a.x + b.x, a.y + b.y);
}
__device__ __forceinline__ float2 f2max(float2 a, float2 b) {
    return make_float2(fmaxf(a.x, b.x), fmaxf(a.y, b.y));
}
__device__ __forceinline__ __half2 asH2(uint32_t u) { return *(__half2*)&u; }
__device__ __forceinline__ float2 ldPf(const uint32_t* p) {
    uint32_t u = __ldg(p);
    return __half22float2(asH2(u));
}

__global__ void __launch_bounds__(512) tree_kernel(const int* __restrict__ tokens,
                                                   float* __restrict__ out) {
    __shared__ __align__(16) int stok[1024];   // token i at stok[i+1] (alignment shift)
    __shared__ float2 bufA[64 * 32];           // 16 KB
    __shared__ float2 bufB[32 * 32];           //  8 KB

    const int bh   = blockIdx.x;
    const int b    = bh >> 1;
    const int chb  = (bh & 1) << 6;
    const int tid  = threadIdx.x;
    const int lane = tid & 31;
    const int grp  = tid >> 5;           // 0..15
    const int* tokrow = tokens + (size_t)b * NNODES;

    for (int i = tid; i < NNODES; i += 512) stok[i + 1] = tokrow[i];

    cudaGridDependencySynchronize();
    __syncthreads();

    const uint32_t* Pc = (const uint32_t*)g_Ph + (chb >> 1) + lane;
    float2 maxv = make_float2(-3.4e38f, -3.4e38f);
    __half2 hmax = __float2half2_rn(-65504.f);

    #pragma unroll
    for (int mi = 0; mi < 4; mi++) {
        int m = grp + mi * 16;
        int q = 63 + m;
        int  tq  = stok[q + 1];
        int2 t2  = *(const int2*)&stok[2 * q + 2];
        int4 t4v = *(const int4*)&stok[4 * q + 4];
        int4 t8a = *(const int4*)&stok[8 * q + 8];
        int4 t8b = *(const int4*)&stok[8 * q + 12];

        uint32_t uq, u2[2], u4[4], u8[8];
        uq    = __ldg(Pc + (size_t)tq * 64);
        u2[0] = __ldg(Pc + (size_t)t2.x * 64);
        u2[1] = __ldg(Pc + (size_t)t2.y * 64);
        u4[0] = __ldg(Pc + (size_t)t4v.x * 64);
        u4[1] = __ldg(Pc + (size_t)t4v.y * 64);
        u4[2] = __ldg(Pc + (size_t)t4v.z * 64);
        u4[3] = __ldg(Pc + (size_t)t4v.w * 64);
        u8[0] = __ldg(Pc + (size_t)t8a.x * 64);
        u8[1] = __ldg(Pc + (size_t)t8a.y * 64);
        u8[2] = __ldg(Pc + (size_t)t8a.z * 64);
        u8[3] = __ldg(Pc + (size_t)t8a.w * 64);
        u8[4] = __ldg(Pc + (size_t)t8b.x * 64);
        u8[5] = __ldg(Pc + (size_t)t8b.y * 64);
        u8[6] = __ldg(Pc + (size_t)t8b.z * 64);
        u8[7] = __ldg(Pc + (size_t)t8b.w * 64);

        __half2 lm01 = __hmax2(asH2(u8[0]), asH2(u8[1]));
        __half2 lm23 = __hmax2(asH2(u8[2]), asH2(u8[3]));
        __half2 lm45 = __hmax2(asH2(u8[4]), asH2(u8[5]));
        __half2 lm67 = __hmax2(asH2(u8[6]), asH2(u8[7]));
        hmax = __hmax2(hmax, __hmax2(__hmax2(lm01, lm23), __hmax2(lm45, lm67)));

        __half2 s8h[4];
        #pragma unroll
        for (int j = 0; j < 4; j++) {
            s8h[j] = __hadd2(asH2(u4[j]), __hadd2(asH2(u8[2 * j]), asH2(u8[2 * j + 1])));
            hmax = __hmax2(hmax, s8h[j]);
        }

        float2 f80 = __half22float2(s8h[0]);
        float2 f81 = __half22float2(s8h[1]);
        float2 f82 = __half22float2(s8h[2]);
        float2 f83 = __half22float2(s8h[3]);
        float2 s70 = f2add(__half22float2(asH2(u2[0])), f2add(f80, f81));
        float2 s71 = f2add(__half22float2(asH2(u2[1])), f2add(f82, f83));
        maxv = f2max(maxv, f2max(s70, s71));
        float2 s6 = f2add(__half22float2(asH2(uq)), f2add(s70, s71));
        maxv = f2max(maxv, s6);
        bufA[m * 32 + lane] = s6;
    }
    maxv = f2max(maxv, __half22float2(hmax));
    __syncthreads();

    #pragma unroll
    for (int ii = 0; ii < 2; ii++) {             // l5: A(64)->B(32)
        int i = grp + ii * 16;
        float2 v = f2add(f2add(bufA[(2 * i) * 32 + lane], bufA[(2 * i + 1) * 32 + lane]),
                         ldPf(Pc + (size_t)stok[32 + i] * 64));
        maxv = f2max(maxv, v);
        bufB[i * 32 + lane] = v;
    }
    __syncthreads();
    {                                            // l4: B(32)->A(16)
        int i = grp;
        float2 v = f2add(f2add(bufB[(2 * i) * 32 + lane], bufB[(2 * i + 1) * 32 + lane]),
                         ldPf(Pc + (size_t)stok[16 + i] * 64));
        maxv = f2max(maxv, v);
        bufA[i * 32 + lane] = v;
    }
    __syncthreads();
    if (grp < 8) {                               // l3: A(16)->B(8)
        int i = grp;
        float2 v = f2add(f2add(bufA[(2 * i) * 32 + lane], bufA[(2 * i + 1) * 32 + lane]),
                         ldPf(Pc + (size_t)stok[8 + i] * 64));
        maxv = f2max(maxv, v);
        bufB[i * 32 + lane] = v;
    }
    __syncthreads();
    if (grp < 4) {                               // l2: B(8)->A(4)
        int i = grp;
        float2 v = f2add(f2add(bufB[(2 * i) * 32 + lane], bufB[(2 * i + 1) * 32 + lane]),
                         ldPf(Pc + (size_t)stok[4 + i] * 64));
        maxv = f2max(maxv, v);
        bufA[i * 32 + lane] = v;
    }
    __syncthreads();
    if (grp < 2) {                               // l1: A(4)->B(2)
        int i = grp;
        float2 v = f2add(f2add(bufA[(2 * i) * 32 + lane], bufA[(2 * i + 1) * 32 + lane]),
                         ldPf(Pc + (size_t)stok[2 + i] * 64));
        maxv = f2max(maxv, v);
        bufB[i * 32 + lane] = v;
    }
    __syncthreads();
    if (grp == 0) {                              // l0: root
        float2 v = f2add(f2add(bufB[lane], bufB[32 + lane]),
                         ldPf(Pc + (size_t)stok[1] * 64));
        maxv = f2max(maxv, v);
    }

    bufA[grp * 32 + lane] = maxv;
    __syncthreads();
    if (grp == 0) {
        float2 m = bufA[lane];
        #pragma unroll
        for (int g = 1; g < 16; g++) m = f2max(m, bufA[g * 32 + lane]);
        *(float2*)(out + (size_t)b * 128 + chb + 2 * lane) = m;
    }
}

// ---------------------------------------------------------------------------
// kernel_launch: pmat, then tree with PDL.
// ---------------------------------------------------------------------------
extern "C" void kernel_launch(void* const* d_in, const int* in_sizes, int n_in,
                              void* d_out, int out_size) {
    const int*   tokens = (const int*)d_in[0];
    const float* emb    = (const float*)d_in[1];
    const float* Wc     = (const float*)d_in[2];
    const float* bc     = (const float*)d_in[3];
    float*       out    = (float*)d_out;

    const int smemA = 2 * 34816;   // 69632 B -> 2 CTAs/SM
    cudaFuncSetAttribute(pmat_kernel, cudaFuncAttributeMaxDynamicSharedMemorySize, smemA);

    const int gridA = (VOCAB + MT - 1) / MT;   // 235
    pmat_kernel<<<gridA, 256, smemA>>>(emb, Wc, bc);

    cudaLaunchConfig_t cfg = {};
    cfg.gridDim  = dim3(BS * 2, 1, 1);
    cfg.blockDim = dim3(512, 1, 1);
    cfg.dynamicSmemBytes = 0;
    cudaLaunchAttribute attrs[1];
    attrs[0].id = cudaLaunchAttributeProgrammaticStreamSerialization;
    attrs[0].val.programmaticStreamSerializationAllowed = 1;
    cfg.attrs = attrs;
    cfg.numAttrs = 1;
    cudaLaunchKernelEx(&cfg, tree_kernel, tokens, out);
}

// round 14
// speedup vs baseline: 1.2318x; 1.1117x over previous
#include <cuda_runtime.h>
#include <cuda_fp16.h>
#include <cstdint>

#define VOCAB 30000
#define EMB 128
#define ENC 128
#define BS 256
#define NNODES 1023

// Precomputed P[t][o] = dot(emb[t,:], W_c[o,:]) + b_c[o], stored fp16 (7.7 MB).
__device__ __half g_Ph[VOCAB * ENC];

// ---------------------------------------------------------------------------
// Kernel A: P = emb @ W_c^T + b_c via mma.sync m16n8k16 fp16 (HMMA, fp32 acc).
//   (unchanged from R13: MT=128, 235 CTAs, 2 CTA/SM, one wave, PDL trigger)
// ---------------------------------------------------------------------------
#define MT 128
#define SAS 136   // smem row stride in fp16 elements (272 B: ldmatrix conflict-free)

#define MMA16816(c, a, b)                                                   \
    asm("mma.sync.aligned.m16n8k16.row.col.f32.f16.f16.f32 "                \
        "{%0,%1,%2,%3}, {%4,%5,%6,%7}, {%8,%9}, {%0,%1,%2,%3};"             \
        : "+f"((c)[0]), "+f"((c)[1]), "+f"((c)[2]), "+f"((c)[3])            \
        : "r"((a)[0]), "r"((a)[1]), "r"((a)[2]), "r"((a)[3]),               \
          "r"((b)[0]), "r"((b)[1]))

#define LDMX4(r, addr)                                                      \
    asm volatile("ldmatrix.sync.aligned.m8n8.x4.shared.b16 "                \
                 "{%0,%1,%2,%3}, [%4];"                                     \
                 : "=r"((r)[0]), "=r"((r)[1]), "=r"((r)[2]), "=r"((r)[3])   \
                 : "r"(addr))

__device__ __forceinline__ uint32_t su32(const void* p) {
    return (uint32_t)__cvta_generic_to_shared(p);
}

__device__ __forceinline__ void cvt_store(uint16_t* __restrict__ dst, int off, float4 x) {
    __half2 p01 = __floats2half2_rn(x.x, x.y);
    __half2 p23 = __floats2half2_rn(x.z, x.w);
    *(uint2*)(dst + off) = make_uint2(*(uint32_t*)&p01, *(uint32_t*)&p23);
}

__global__ void __launch_bounds__(256) pmat_kernel(const float* __restrict__ emb,
                                                   const float* __restrict__ Wc,
                                                   const float* __restrict__ bc) {
    extern __shared__ __align__(16) char dsm[];
    uint16_t* sA = (uint16_t*)dsm;                     // 128*136*2 = 34816 B
    uint16_t* sB = (uint16_t*)(dsm + 34816);           // 34816 B
    __shared__ float s_bias[128];

    const int tid = threadIdx.x;
    const int row0 = blockIdx.x * MT;

    if (tid < 128) s_bias[tid] = bc[tid];

    #pragma unroll 4
    for (int i = tid; i < MT * 32; i += 256) {
        int r = i >> 5, q = (i & 31) * 4;
        float4 x = make_float4(0.f, 0.f, 0.f, 0.f);
        if (row0 + r < VOCAB) x = *(const float4*)(emb + (size_t)(row0 + r) * 128 + q);
        cvt_store(sA, r * SAS + q, x);
    }
    #pragma unroll 4
    for (int i = tid; i < 128 * 32; i += 256) {
        int r = i >> 5, q = (i & 31) * 4;
        float4 w = *(const float4*)(Wc + (size_t)r * 128 + q);
        cvt_store(sB, r * SAS + q, w);
    }
    __syncthreads();

    const int warp = tid >> 5, lane = tid & 31;
    const int grp = lane >> 2, t4 = lane & 3;
    const int quad = lane >> 3, r8 = lane & 7;
    const int m0 = (warp & 3) * 32;        // 4 m-groups
    const int n0 = (warp >> 2) * 64;       // 2 n-halves

    uint32_t aA[2];
    #pragma unroll
    for (int mt = 0; mt < 2; mt++) {
        int rowA = m0 + mt * 16 + (quad & 1) * 8 + r8;
        int kA = (quad >> 1) * 8;
        aA[mt] = su32(sA) + (rowA * SAS + kA) * 2;
    }
    uint32_t aB[4];
    #pragma unroll
    for (int i = 0; i < 4; i++) {
        int rowB = n0 + i * 16 + (quad >> 1) * 8 + r8;
        int kB = (quad & 1) * 8;
        aB[i] = su32(sB) + (rowB * SAS + kB) * 2;
    }

    float acc[2][8][4];
    #pragma unroll
    for (int mt = 0; mt < 2; mt++)
        #pragma unroll
        for (int nt = 0; nt < 8; nt++)
            #pragma unroll
            for (int j = 0; j < 4; j++) acc[mt][nt][j] = 0.f;

    #pragma unroll
    for (int ks = 0; ks < 8; ks++) {
        const uint32_t off = ks * 32;
        uint32_t a[2][4];
        LDMX4(a[0], aA[0] + off);
        LDMX4(a[1], aA[1] + off);
        uint32_t bp[4][4];
        LDMX4(bp[0], aB[0] + off);
        LDMX4(bp[1], aB[1] + off);
        LDMX4(bp[2], aB[2] + off);
        LDMX4(bp[3], aB[3] + off);
        #pragma unroll
        for (int mt = 0; mt < 2; mt++)
            #pragma unroll
            for (int nt = 0; nt < 8; nt++) {
                uint32_t* bb = &bp[nt >> 1][(nt & 1) * 2];
                MMA16816(acc[mt][nt], a[mt], bb);
            }
    }

    #pragma unroll
    for (int mt = 0; mt < 2; mt++) {
        #pragma unroll
        for (int nt = 0; nt < 8; nt++) {
            int col = n0 + nt * 8 + t4 * 2;
            float b0 = s_bias[col], b1 = s_bias[col + 1];
            int r_lo = row0 + m0 + mt * 16 + grp;
            if (r_lo < VOCAB) {
                __half2 v = __floats2half2_rn(acc[mt][nt][0] + b0, acc[mt][nt][1] + b1);
                *(__half2*)(g_Ph + (size_t)r_lo * 128 + col) = v;
            }
            int r_hi = r_lo + 8;
            if (r_hi < VOCAB) {
                __half2 v = __floats2half2_rn(acc[mt][nt][2] + b0, acc[mt][nt][3] + b1);
                *(__half2*)(g_Ph + (size_t)r_hi * 128 + col) = v;
            }
        }
    }

    cudaTriggerProgrammaticLaunchCompletion();
}

// ---------------------------------------------------------------------------
// Kernel B: ONE CTA per batch (256 CTAs x 512 thr). Lane covers 4 channels
//   via uint2 (LDG.64, 256 B/warp = whole node row) -> gather instruction
//   count halved vs (batch, ch-half) split. Warp grp owns contiguous subtrees
//   m = 4*grp..4*grp+3, so levels 5 and 4 fold in registers (no bufA, -2
//   barriers). Levels 9+8 in fp16, rest fp32.
// ---------------------------------------------------------------------------
__device__ __forceinline__ float4 f4add(float4 a, float4 b) {
    return make_float4(a.x + b.x, a.y + b.y, a.z + b.z, a.w + b.w);
}
__device__ __forceinline__ float4 f4max(float4 a, float4 b) {
    return make_float4(fmaxf(a.x, b.x), fmaxf(a.y, b.y),
                       fmaxf(a.z, b.z), fmaxf(a.w, b.w));
}
__device__ __forceinline__ __half2 asH2(uint32_t u) { return *(__half2*)&u; }
__device__ __forceinline__ float4 c4(uint2 u) {
    float2 lo = __half22float2(asH2(u.x));
    float2 hi = __half22float2(asH2(u.y));
    return make_float4(lo.x, lo.y, hi.x, hi.y);
}

__global__ void __launch_bounds__(512, 2) tree_kernel(const int* __restrict__ tokens,
                                                      float* __restrict__ out) {
    __shared__ __align__(16) int stok[1024];   // token i at stok[i+1] (alignment shift)
    __shared__ float4 bufX[16 * 32];           // 8 KB (l4 out; reused as max scratch)
    __shared__ float4 bufY[8 * 32];            // 4 KB (l3/l1 out)

    const int b    = blockIdx.x;
    const int tid  = threadIdx.x;
    const int lane = tid & 31;
    const int grp  = tid >> 5;           // 0..15
    const int* tokrow = tokens + (size_t)b * NNODES;

    for (int i = tid; i < NNODES; i += 512) stok[i + 1] = tokrow[i];

    cudaGridDependencySynchronize();     // PDL: wait for pmat's P stores
    __syncthreads();

    // node t -> Pc[t*32]; each uint2 = 4 channels (2 x half2)
    const uint2* Pc = (const uint2*)g_Ph + lane;

    float4 maxv = make_float4(-3.4e38f, -3.4e38f, -3.4e38f, -3.4e38f);
    __half2 hmaxA = __float2half2_rn(-65504.f);   // channels 4l, 4l+1
    __half2 hmaxB = __float2half2_rn(-65504.f);   // channels 4l+2, 4l+3
    float4 v5a = make_float4(0.f, 0.f, 0.f, 0.f);
    float4 v5b = make_float4(0.f, 0.f, 0.f, 0.f);

    // fused levels 9..6: warp grp owns subtrees m = 4*grp + mi
    #pragma unroll
    for (int mi = 0; mi < 4; mi++) {
        int m = grp * 4 + mi;
        int q = 63 + m;
        int  tq  = stok[q + 1];
        int2 t2  = *(const int2*)&stok[2 * q + 2];
        int4 t4v = *(const int4*)&stok[4 * q + 4];
        int4 t8a = *(const int4*)&stok[8 * q + 8];
        int4 t8b = *(const int4*)&stok[8 * q + 12];

        uint2 uq, u2[2], u4[4], u8[8];
        uq    = __ldg(Pc + (size_t)tq * 32);
        u2[0] = __ldg(Pc + (size_t)t2.x * 32);
        u2[1] = __ldg(Pc + (size_t)t2.y * 32);
        u4[0] = __ldg(Pc + (size_t)t4v.x * 32);
        u4[1] = __ldg(Pc + (size_t)t4v.y * 32);
        u4[2] = __ldg(Pc + (size_t)t4v.z * 32);
        u4[3] = __ldg(Pc + (size_t)t4v.w * 32);
        u8[0] = __ldg(Pc + (size_t)t8a.x * 32);
        u8[1] = __ldg(Pc + (size_t)t8a.y * 32);
        u8[2] = __ldg(Pc + (size_t)t8a.z * 32);
        u8[3] = __ldg(Pc + (size_t)t8a.w * 32);
        u8[4] = __ldg(Pc + (size_t)t8b.x * 32);
        u8[5] = __ldg(Pc + (size_t)t8b.y * 32);
        u8[6] = __ldg(Pc + (size_t)t8b.z * 32);
        u8[7] = __ldg(Pc + (size_t)t8b.w * 32);

        // leaf max (exact fp16 compares, both half2 lanes)
        __half2 lmA = __hmax2(__hmax2(asH2(u8[0].x), asH2(u8[1].x)),
                              __hmax2(asH2(u8[2].x), asH2(u8[3].x)));
        lmA = __hmax2(lmA, __hmax2(__hmax2(asH2(u8[4].x), asH2(u8[5].x)),
                                   __hmax2(asH2(u8[6].x), asH2(u8[7].x))));
        hmaxA = __hmax2(hmaxA, lmA);
        __half2 lmB = __hmax2(__hmax2(asH2(u8[0].y), asH2(u8[1].y)),
                              __hmax2(asH2(u8[2].y), asH2(u8[3].y)));
        lmB = __hmax2(lmB, __hmax2(__hmax2(asH2(u8[4].y), asH2(u8[5].y)),
                                   __hmax2(asH2(u8[6].y), asH2(u8[7].y))));
        hmaxB = __hmax2(hmaxB, lmB);

        // level-8 sums in fp16
        uint2 s8h[4];
        #pragma unroll
        for (int j = 0; j < 4; j++) {
            __half2 sx = __hadd2(asH2(u4[j].x), __hadd2(asH2(u8[2 * j].x), asH2(u8[2 * j + 1].x)));
            __half2 sy = __hadd2(asH2(u4[j].y), __hadd2(asH2(u8[2 * j].y), asH2(u8[2 * j + 1].y)));
            hmaxA = __hmax2(hmaxA, sx);
            hmaxB = __hmax2(hmaxB, sy);
            s8h[j].x = *(uint32_t*)&sx;
            s8h[j].y = *(uint32_t*)&sy;
        }

        // levels 7, 6 in fp32
        float4 s70 = f4add(c4(u2[0]), f4add(c4(s8h[0]), c4(s8h[1])));
        float4 s71 = f4add(c4(u2[1]), f4add(c4(s8h[2]), c4(s8h[3])));
        maxv = f4max(maxv, f4max(s70, s71));
        float4 s6 = f4add(c4(uq), f4add(s70, s71));
        maxv = f4max(maxv, s6);

        // level-5 partial sums in registers (sibling pairs owned by this warp)
        if (mi == 0) v5a = s6;
        else if (mi == 1) v5a = f4add(v5a, s6);
        else if (mi == 2) v5b = s6;
        else v5b = f4add(v5b, s6);
    }
    maxv = f4max(maxv, make_float4(__half22float2(hmaxA).x, __half22float2(hmaxA).y,
                                   __half22float2(hmaxB).x, __half22float2(hmaxB).y));

    // levels 5 and 4 in registers
    v5a = f4add(v5a, c4(__ldg(Pc + (size_t)stok[32 + 2 * grp] * 32)));
    v5b = f4add(v5b, c4(__ldg(Pc + (size_t)stok[33 + 2 * grp] * 32)));
    maxv = f4max(maxv, f4max(v5a, v5b));
    float4 v4 = f4add(f4add(v5a, v5b), c4(__ldg(Pc + (size_t)stok[16 + grp] * 32)));
    maxv = f4max(maxv, v4);
    bufX[grp * 32 + lane] = v4;
    __syncthreads();

    if (grp < 8) {                               // l3: X(16)->Y(8)
        int i = grp;
        float4 v = f4add(f4add(bufX[(2 * i) * 32 + lane], bufX[(2 * i + 1) * 32 + lane]),
                         c4(__ldg(Pc + (size_t)stok[8 + i] * 32)));
        maxv = f4max(maxv, v);
        bufY[i * 32 + lane] = v;
    }
    __syncthreads();
    if (grp < 4) {                               // l2: Y(8)->X(4)
        int i = grp;
        float4 v = f4add(f4add(bufY[(2 * i) * 32 + lane], bufY[(2 * i + 1) * 32 + lane]),
                         c4(__ldg(Pc + (size_t)stok[4 + i] * 32)));
        maxv = f4max(maxv, v);
        bufX[i * 32 + lane] = v;
    }
    __syncthreads();
    if (grp < 2) {                               // l1: X(4)->Y(2)
        int i = grp;
        float4 v = f4add(f4add(bufX[(2 * i) * 32 + lane], bufX[(2 * i + 1) * 32 + lane]),
                         c4(__ldg(Pc + (size_t)stok[2 + i] * 32)));
        maxv = f4max(maxv, v);
        bufY[i * 32 + lane] = v;
    }
    __syncthreads();
    if (grp == 0) {                              // l0: root
        float4 v = f4add(f4add(bufY[lane], bufY[32 + lane]),
                         c4(__ldg(Pc + (size_t)stok[1] * 32)));
        maxv = f4max(maxv, v);
    }
    __syncthreads();                             // bufX reuse (l1 read rows 0..3)

    // cross-group max (bufX as scratch [grp][lane])
    bufX[grp * 32 + lane] = maxv;
    __syncthreads();
    if (grp == 0) {
        float4 m = bufX[lane];
        #pragma unroll
        for (int g = 1; g < 16; g++) m = f4max(m, bufX[g * 32 + lane]);
        *(float4*)(out + (size_t)b * 128 + lane * 4) = m;
    }
}

// ---------------------------------------------------------------------------
// kernel_launch: pmat, then tree with PDL.
// ---------------------------------------------------------------------------
extern "C" void kernel_launch(void* const* d_in, const int* in_sizes, int n_in,
                              void* d_out, int out_size) {
    const int*   tokens = (const int*)d_in[0];
    const float* emb    = (const float*)d_in[1];
    const float* Wc     = (const float*)d_in[2];
    const float* bc     = (const float*)d_in[3];
    float*       out    = (float*)d_out;

    const int smemA = 2 * 34816;   // 69632 B -> 2 CTAs/SM
    cudaFuncSetAttribute(pmat_kernel, cudaFuncAttributeMaxDynamicSharedMemorySize, smemA);

    const int gridA = (VOCAB + MT - 1) / MT;   // 235
    pmat_kernel<<<gridA, 256, smemA>>>(emb, Wc, bc);

    cudaLaunchConfig_t cfg = {};
    cfg.gridDim  = dim3(BS, 1, 1);
    cfg.blockDim = dim3(512, 1, 1);
    cfg.dynamicSmemBytes = 0;
    cudaLaunchAttribute attrs[1];
    attrs[0].id = cudaLaunchAttributeProgrammaticStreamSerialization;
    attrs[0].val.programmaticStreamSerializationAllowed = 1;
    cfg.attrs = attrs;
    cfg.numAttrs = 1;
    cudaLaunchKernelEx(&cfg, tree_kernel, tokens, out);
}